// round 1
// baseline (speedup 1.0000x reference)
#include <cuda_runtime.h>

#define BATCH 8
#define CH    384
#define NH    8
#define HD    48
#define SEQ   1024
#define O3    1152   // 3*CH

// Scratch (device globals — allocation-free per harness rules)
__device__ float g_qkv[(size_t)BATCH * O3 * SEQ];   // [b][o][p], o in [0,1152)
__device__ float g_ao [(size_t)BATCH * CH * SEQ];   // attention output, [b][c][p]

// ---------------------------------------------------------------------------
// 1x1-conv GEMM:  Out[b][o][p] = sum_c W[o][c] * X[b][c][p]  (+ bias if proj)
// BM=BN=64, BK=16, 256 threads, 4x4 per-thread tile.
// ---------------------------------------------------------------------------
template<int M_CH, int IS_PROJ>
__global__ __launch_bounds__(256)
void gemm1x1_kernel(const float* __restrict__ W,
                    const float* __restrict__ Xparam,
                    const float* __restrict__ bias,
                    float* __restrict__ Outparam)
{
    __shared__ float As[16][64];   // [k][m] (A transposed)
    __shared__ float Bs[16][64];   // [k][n]

    const float* Xall = IS_PROJ ? g_ao : Xparam;
    float*       Out  = IS_PROJ ? Outparam : g_qkv;

    const int b  = blockIdx.z;
    const int o0 = blockIdx.y * 64;
    const int p0 = blockIdx.x * 64;
    const float* X = Xall + (size_t)b * CH * SEQ;

    const int tid  = threadIdx.x;
    const int trow = tid >> 4;   // 0..15
    const int tcol = tid & 15;   // 0..15

    float acc[4][4];
#pragma unroll
    for (int m = 0; m < 4; m++)
#pragma unroll
        for (int n = 0; n < 4; n++) acc[m][n] = 0.f;

    const int ai = tid >> 2;          // 0..63 (A row within tile)
    const int ac = (tid & 3) << 2;    // 0,4,8,12 (A k-offset)
    const int bi = tid >> 4;          // 0..15 (B k-row)
    const int bj = (tid & 15) << 2;   // 0..60 (B col, float4)

    for (int k0 = 0; k0 < CH; k0 += 16) {
        float4 a4 = *reinterpret_cast<const float4*>(W + (size_t)(o0 + ai) * CH + k0 + ac);
        float4 b4 = *reinterpret_cast<const float4*>(X + (size_t)(k0 + bi) * SEQ + p0 + bj);
        As[ac + 0][ai] = a4.x;
        As[ac + 1][ai] = a4.y;
        As[ac + 2][ai] = a4.z;
        As[ac + 3][ai] = a4.w;
        *reinterpret_cast<float4*>(&Bs[bi][bj]) = b4;
        __syncthreads();
#pragma unroll
        for (int kk = 0; kk < 16; kk++) {
            float4 af = *reinterpret_cast<const float4*>(&As[kk][trow << 2]);
            float4 bf = *reinterpret_cast<const float4*>(&Bs[kk][tcol << 2]);
            float a[4]  = {af.x, af.y, af.z, af.w};
            float bb[4] = {bf.x, bf.y, bf.z, bf.w};
#pragma unroll
            for (int m = 0; m < 4; m++)
#pragma unroll
                for (int n = 0; n < 4; n++) acc[m][n] += a[m] * bb[n];
        }
        __syncthreads();
    }

#pragma unroll
    for (int m = 0; m < 4; m++) {
        int o = o0 + (trow << 2) + m;
        float bv = IS_PROJ ? bias[o] : 0.f;
        float4 v = make_float4(acc[m][0] + bv, acc[m][1] + bv,
                               acc[m][2] + bv, acc[m][3] + bv);
        *reinterpret_cast<float4*>(Out + ((size_t)b * M_CH + o) * SEQ + p0 + (tcol << 2)) = v;
    }
}

// ---------------------------------------------------------------------------
// Flash-style attention: one query row per thread, 32-key tiles in smem.
// Q/K/V are read channel-major from g_qkv (coalesced across threads).
// Output written channel-major to g_ao for the proj GEMM.
// ---------------------------------------------------------------------------
__global__ __launch_bounds__(128)
void attn_kernel()
{
    __shared__ float4 Ks[HD * 8];   // [d=48][j4=8] -> K tile [48][32] floats
    __shared__ float4 Vs[HD * 8];

    const int bh = blockIdx.y;            // b*8 + h
    const int b  = bh >> 3;
    const int h  = bh & 7;
    const int r  = blockIdx.x * 128 + threadIdx.x;   // query index (pixel)

    const float* qbase = g_qkv + ((size_t)b * O3 +           h * HD) * SEQ;
    const float* kbase = g_qkv + ((size_t)b * O3 + CH      + h * HD) * SEQ;
    const float* vbase = g_qkv + ((size_t)b * O3 + 2 * CH  + h * HD) * SEQ;

    const float scale = 0.14433756729740643f;   // 48^-0.5

    float q[HD];
#pragma unroll
    for (int d = 0; d < HD; d++) q[d] = qbase[(size_t)d * SEQ + r] * scale;

    float o[HD];
#pragma unroll
    for (int d = 0; d < HD; d++) o[d] = 0.f;

    float mrun = -1e30f;
    float lrun = 0.f;

    for (int j0 = 0; j0 < SEQ; j0 += 32) {
        __syncthreads();   // previous tile fully consumed
        for (int idx = threadIdx.x; idx < HD * 8; idx += 128) {
            int dd = idx >> 3;
            int j4 = idx & 7;
            Ks[idx] = *reinterpret_cast<const float4*>(kbase + (size_t)dd * SEQ + j0 + (j4 << 2));
            Vs[idx] = *reinterpret_cast<const float4*>(vbase + (size_t)dd * SEQ + j0 + (j4 << 2));
        }
        __syncthreads();

        // scores for 32 keys
        float s[32];
#pragma unroll
        for (int j = 0; j < 32; j++) s[j] = 0.f;
#pragma unroll
        for (int d = 0; d < HD; d++) {
            float qd = q[d];
#pragma unroll
            for (int j4 = 0; j4 < 8; j4++) {
                float4 k4 = Ks[d * 8 + j4];   // broadcast LDS.128
                s[j4 * 4 + 0] += qd * k4.x;
                s[j4 * 4 + 1] += qd * k4.y;
                s[j4 * 4 + 2] += qd * k4.z;
                s[j4 * 4 + 3] += qd * k4.w;
            }
        }

        // online softmax update
        float mb = mrun;
#pragma unroll
        for (int j = 0; j < 32; j++) mb = fmaxf(mb, s[j]);
        float f = __expf(mrun - mb);
        mrun = mb;
        lrun *= f;
#pragma unroll
        for (int d = 0; d < HD; d++) o[d] *= f;
#pragma unroll
        for (int j = 0; j < 32; j++) {
            s[j] = __expf(s[j] - mb);   // reuse s[] as p[]
            lrun += s[j];
        }

        // o += p @ V_tile
#pragma unroll
        for (int d = 0; d < HD; d++) {
            float acc = 0.f;
#pragma unroll
            for (int j4 = 0; j4 < 8; j4++) {
                float4 v4 = Vs[d * 8 + j4];   // broadcast LDS.128
                acc += s[j4 * 4 + 0] * v4.x;
                acc += s[j4 * 4 + 1] * v4.y;
                acc += s[j4 * 4 + 2] * v4.z;
                acc += s[j4 * 4 + 3] * v4.w;
            }
            o[d] += acc;
        }
    }

    const float inv = 1.f / lrun;
    float* obase = g_ao + (size_t)bh * HD * SEQ + r;   // b*CH + h*HD == bh*HD
#pragma unroll
    for (int d = 0; d < HD; d++) obase[(size_t)d * SEQ] = o[d] * inv;
}

// ---------------------------------------------------------------------------
extern "C" void kernel_launch(void* const* d_in, const int* in_sizes, int n_in,
                              void* d_out, int out_size)
{
    const float* x      = (const float*)d_in[0];   // [8,384,32,32]
    const float* w_qkv  = (const float*)d_in[1];   // [1152,384]
    const float* w_proj = (const float*)d_in[2];   // [384,384]
    const float* b_proj = (const float*)d_in[3];   // [384]
    float* out = (float*)d_out;                    // [8,384,32,32]

    // Stage 1: QKV = w_qkv @ x   -> g_qkv [b][1152][1024]
    gemm1x1_kernel<O3, 0><<<dim3(SEQ / 64, O3 / 64, BATCH), 256>>>(w_qkv, x, nullptr, nullptr);

    // Stage 2: attention -> g_ao [b][384][1024]
    attn_kernel<<<dim3(SEQ / 128, BATCH * NH), 128>>>();

    // Stage 3: out = w_proj @ g_ao + b_proj
    gemm1x1_kernel<CH, 1><<<dim3(SEQ / 64, CH / 64, BATCH), 256>>>(w_proj, nullptr, b_proj, out);
}